// round 1
// baseline (speedup 1.0000x reference)
#include <cuda_runtime.h>

// Shapes (fixed by the reference):
//   x      [64, 512, 56, 56]  = 102,760,448 fp32
//   ssty   [64, 512, 3, 3]    = 294,912 fp32
//   beta   [1]
//   conv_w [512, 512, 3, 3]   = 2,359,296 fp32
//   conv_b [512]
// out = x * mask[c],  mask = sigmoid(beta * (dot(sum_b ssty, conv_w[c]) + conv_b[c]))

#define C_CH   512
#define KVOL   4608          // 512*3*3
#define BATCH  64
#define HW     3136          // 56*56
#define NTOT   (64u * 512u * 56u * 56u)   // 102,760,448
#define N4     (NTOT / 4u)                // 25,690,112
#define HW4    (HW / 4)                   // 784

__device__ float g_s[KVOL];
__device__ float g_mask[C_CH];

// Kernel 1: s[j] = sum_b ssty[b, j]   (coalesced across j within a warp)
__global__ void reduce_ssty_kernel(const float* __restrict__ ssty) {
    int j = blockIdx.x * blockDim.x + threadIdx.x;
    if (j >= KVOL) return;
    float acc = 0.0f;
    #pragma unroll 8
    for (int b = 0; b < BATCH; ++b)
        acc += ssty[b * KVOL + j];
    g_s[j] = acc;
}

// Kernel 2: one block per output channel; block-reduce the 4608-length dot.
__global__ void __launch_bounds__(256)
compute_mask_kernel(const float* __restrict__ conv_w,
                    const float* __restrict__ conv_b,
                    const float* __restrict__ beta,
                    float* __restrict__ mask_tail,
                    int write_tail) {
    const int c = blockIdx.x;
    const float* __restrict__ w = conv_w + c * KVOL;
    float acc = 0.0f;
    for (int j = threadIdx.x; j < KVOL; j += 256)
        acc += g_s[j] * w[j];

    // warp reduce
    #pragma unroll
    for (int off = 16; off > 0; off >>= 1)
        acc += __shfl_down_sync(0xFFFFFFFFu, acc, off);

    __shared__ float red[8];
    if ((threadIdx.x & 31) == 0) red[threadIdx.x >> 5] = acc;
    __syncthreads();

    if (threadIdx.x == 0) {
        float s = 0.0f;
        #pragma unroll
        for (int i = 0; i < 8; ++i) s += red[i];
        float m = (s + conv_b[c]) * beta[0];
        float msk = 1.0f / (1.0f + expf(-m));
        g_mask[c] = msk;
        if (write_tail) mask_tail[c] = msk;
    }
}

// Kernel 3: out = x * mask[channel], float4-vectorized, streaming hints.
// Element-vector i covers x[4i..4i+3]; channel = (4i / 3136) % 512 = (i / 784) & 511.
__global__ void __launch_bounds__(256)
scale_x_kernel(const float4* __restrict__ x, float4* __restrict__ out) {
    unsigned i = blockIdx.x * 256u + threadIdx.x;
    if (i >= N4) return;
    unsigned c = (i / HW4) & (C_CH - 1);
    float m = g_mask[c];
    float4 v = __ldcs(x + i);
    v.x *= m; v.y *= m; v.z *= m; v.w *= m;
    __stcs(out + i, v);
}

extern "C" void kernel_launch(void* const* d_in, const int* in_sizes, int n_in,
                              void* d_out, int out_size) {
    const float* x      = (const float*)d_in[0];
    const float* ssty   = (const float*)d_in[1];
    const float* beta   = (const float*)d_in[2];
    const float* conv_w = (const float*)d_in[3];
    const float* conv_b = (const float*)d_in[4];
    float* out = (float*)d_out;

    // If the harness concatenates the tuple (out, new_mask), out_size exceeds NTOT
    // and we must also write the 512-element mask at the tail.
    int write_tail = (out_size > (int)NTOT) ? 1 : 0;

    reduce_ssty_kernel<<<(KVOL + 255) / 256, 256>>>(ssty);
    compute_mask_kernel<<<C_CH, 256>>>(conv_w, conv_b, beta, out + NTOT, write_tail);
    scale_x_kernel<<<(N4 + 255u) / 256u, 256>>>((const float4*)x, (float4*)out);
}

// round 2
// speedup vs baseline: 1.0175x; 1.0175x over previous
#include <cuda_runtime.h>

// Shapes (fixed by the reference):
//   x      [64, 512, 56, 56]  = 102,760,448 fp32
//   ssty   [64, 512, 3, 3]    = 294,912 fp32  (= 64 x 4608)
//   beta   [1]
//   conv_w [512, 512, 3, 3]   = 2,359,296 fp32 (= 512 x 4608)
//   conv_b [512]
// out = x * mask[c],  mask = sigmoid(beta * (dot(sum_b ssty, conv_w[c]) + conv_b[c]))

#define C_CH   512
#define KVOL   4608            // 512*3*3
#define KVOL4  1152            // KVOL/4
#define BATCH  64
#define HW     3136            // 56*56
#define NTOT   (64u * 512u * 56u * 56u)   // 102,760,448
#define N4     (NTOT / 4u)                // 25,690,112
#define HW4    784u                       // HW/4

__device__ float4 g_s4[KVOL4];
__device__ float  g_mask[C_CH];

// ─── Kernel 1: s[j] = sum_b ssty[b, j] ───────────────────────────────────────
// 36 blocks x 256 threads. Block = 32 j4-lanes x 8 batch-groups (8 batches each).
// Each thread: 8 independent float4 loads (one DRAM latency deep), smem reduce.
__global__ void __launch_bounds__(256)
reduce_ssty_kernel(const float4* __restrict__ ssty4) {
    const int lane = threadIdx.x & 31;        // j4 lane within chunk
    const int grp  = threadIdx.x >> 5;        // batch group 0..7
    const int j4   = blockIdx.x * 32 + lane;  // 0..1151

    float4 acc = make_float4(0.f, 0.f, 0.f, 0.f);
    #pragma unroll
    for (int b = 0; b < 8; ++b) {
        float4 v = ssty4[(grp * 8 + b) * KVOL4 + j4];
        acc.x += v.x; acc.y += v.y; acc.z += v.z; acc.w += v.w;
    }

    __shared__ float4 red[8][32];
    red[grp][lane] = acc;
    __syncthreads();

    if (grp == 0) {
        float4 t = red[0][lane];
        #pragma unroll
        for (int p = 1; p < 8; ++p) {
            float4 v = red[p][lane];
            t.x += v.x; t.y += v.y; t.z += v.z; t.w += v.w;
        }
        g_s4[j4] = t;
    }
}

// ─── Kernel 2: mask[c] = sigmoid(beta * (dot(s, w[c]) + b[c])) ───────────────
// 512 blocks (one per channel) x 256 threads; s staged to smem, w via float4.
__global__ void __launch_bounds__(256)
compute_mask_kernel(const float4* __restrict__ conv_w4,
                    const float* __restrict__ conv_b,
                    const float* __restrict__ beta,
                    float* __restrict__ mask_tail,
                    int write_tail) {
    const int c = blockIdx.x;

    __shared__ float4 s4[KVOL4];               // 18 KB
    for (int j = threadIdx.x; j < KVOL4; j += 256)
        s4[j] = g_s4[j];
    __syncthreads();

    const float4* __restrict__ w4 = conv_w4 + (size_t)c * KVOL4;
    float acc = 0.0f;
    for (int j = threadIdx.x; j < KVOL4; j += 256) {
        float4 wv = w4[j];
        float4 sv = s4[j];
        acc += wv.x * sv.x + wv.y * sv.y + wv.z * sv.z + wv.w * sv.w;
    }

    #pragma unroll
    for (int off = 16; off > 0; off >>= 1)
        acc += __shfl_down_sync(0xFFFFFFFFu, acc, off);

    __shared__ float red[8];
    if ((threadIdx.x & 31) == 0) red[threadIdx.x >> 5] = acc;
    __syncthreads();

    if (threadIdx.x == 0) {
        float s = 0.0f;
        #pragma unroll
        for (int i = 0; i < 8; ++i) s += red[i];
        float m   = (s + conv_b[c]) * beta[0];
        float msk = 1.0f / (1.0f + expf(-m));
        g_mask[c] = msk;
        if (write_tail) mask_tail[c] = msk;
    }
}

// ─── Kernel 3: out = x * mask[channel] ───────────────────────────────────────
// 4 float4s per thread, block tile = 1024 vec4 (N4 = 25088 * 1024 exactly).
// channel of vec i = (i / 784) & 511.
__global__ void __launch_bounds__(256)
scale_x_kernel(const float4* __restrict__ x, float4* __restrict__ out) {
    unsigned base = blockIdx.x * 1024u + threadIdx.x;
    #pragma unroll
    for (int k = 0; k < 4; ++k) {
        unsigned i = base + k * 256u;
        unsigned c = (i / HW4) & (C_CH - 1);
        float m = g_mask[c];
        float4 v = __ldcs(x + i);
        v.x *= m; v.y *= m; v.z *= m; v.w *= m;
        __stcs(out + i, v);
    }
}

extern "C" void kernel_launch(void* const* d_in, const int* in_sizes, int n_in,
                              void* d_out, int out_size) {
    const float* x      = (const float*)d_in[0];
    const float* ssty   = (const float*)d_in[1];
    const float* beta   = (const float*)d_in[2];
    const float* conv_w = (const float*)d_in[3];
    const float* conv_b = (const float*)d_in[4];
    float* out = (float*)d_out;

    int write_tail = (out_size > (int)NTOT) ? 1 : 0;

    reduce_ssty_kernel<<<KVOL4 / 32, 256>>>((const float4*)ssty);
    compute_mask_kernel<<<C_CH, 256>>>((const float4*)conv_w, conv_b, beta,
                                       out + NTOT, write_tail);
    scale_x_kernel<<<N4 / 1024u, 256>>>((const float4*)x, (float4*)out);
}